// round 14
// baseline (speedup 1.0000x reference)
#include <cuda_runtime.h>
#include <cuda_fp16.h>

#define HID 128
#define MLPD 64
#define MAX_NODES 50000
#define TILE_N 32
#define ES_PAD 132          // n-major emb tile row stride (floats), 16B-aligned, conflict-free

// Scratch: per-node projections in FP16.
// P[n][0:64] = emb[n] @ W1[0:128] + b1 ;  P[n][64:128] = emb[n] @ W1[128:256]
__device__ __half g_Ph[(size_t)MAX_NODES * HID];

#define FMA2(d, a, b, c) \
    asm("fma.rn.f32x2 %0, %1, %2, %3;" : "=l"(d) : "l"(a), "l"(b), "l"(c))
#define ADD2(d, a, b) \
    asm("add.rn.f32x2 %0, %1, %2;" : "=l"(d) : "l"(a), "l"(b))
#define DUP2(d, f) \
    asm("mov.b64 %0, {%1, %1};" : "=l"(d) : "r"(__float_as_uint(f)))

__device__ __forceinline__ float2 unpack2(unsigned long long v) {
    unsigned int lo, hi;
    asm("mov.b64 {%0, %1}, %2;" : "=r"(lo), "=r"(hi) : "l"(v));
    return make_float2(__uint_as_float(lo), __uint_as_float(hi));
}

// ---------------------------------------------------------------------------
// Kernel A: node projection  [n_nodes,128] x [128->128] -> P (fp16)
// Warp-as-column-unit: lane = node, warp w owns output cols [16w,16w+16).
// W reads are LDS.128 broadcasts (crossbar-cheap); e is one scalar/thread/k.
// Single pass over both W1 halves via transposed Wt[k][c] tile (64KB dynamic).
// ---------------------------------------------------------------------------
#define WT_FLOATS (HID * HID)            // 16384 -> 64KB
#define ES_FLOATS (TILE_N * ES_PAD)      // 4224  -> 16.9KB
#define PROJ_SMEM ((WT_FLOATS + ES_FLOATS) * 4)

__global__ void __launch_bounds__(256) proj_kernel(
    const float* __restrict__ emb,   // [n_nodes, 128]
    const float* __restrict__ W1,    // [256, 64] row-major
    const float* __restrict__ b1,    // [64]
    __half* __restrict__ P,
    int n_nodes)
{
    extern __shared__ float smem[];
    float* Wt = smem;                 // Wt[k][c], c in [0,128): fused both halves
    float* Es = smem + WT_FLOATS;     // Es[n][k], row stride ES_PAD

    const int tid  = threadIdx.x;
    const int base = blockIdx.x * TILE_N;

    // Wt[k][c] = W1[k][c] (c<64)  |  W1[128+k][c-64] (c>=64)
    #pragma unroll
    for (int i = tid; i < WT_FLOATS; i += 256) {
        int k = i >> 7, c = i & 127;
        Wt[i] = W1[((c >> 6) << 13) + k * MLPD + (c & 63)];
    }
    // Es[n][k] (coalesced gmem reads)
    #pragma unroll
    for (int i = tid; i < TILE_N * HID; i += 256) {
        int n = i >> 7, k = i & 127;
        int node = base + n;
        Es[n * ES_PAD + k] = (node < n_nodes) ? emb[(size_t)node * HID + k] : 0.0f;
    }
    __syncthreads();

    const int lane = tid & 31;        // node within tile
    const int w    = tid >> 5;        // warp -> column block
    const int c0   = w * 16;

    unsigned long long acc[8];
    #pragma unroll
    for (int j = 0; j < 8; j++) acc[j] = 0ull;

    const float* erow = &Es[lane * ES_PAD];

    #pragma unroll 4
    for (int k = 0; k < HID; k += 4) {
        float4 ev = *reinterpret_cast<const float4*>(erow + k);
        #pragma unroll
        for (int kk = 0; kk < 4; kk++) {
            const float* wr = &Wt[(k + kk) * HID + c0];     // warp-uniform -> broadcast
            ulonglong2 wa = *reinterpret_cast<const ulonglong2*>(wr);
            ulonglong2 wb = *reinterpret_cast<const ulonglong2*>(wr + 4);
            ulonglong2 wc = *reinterpret_cast<const ulonglong2*>(wr + 8);
            ulonglong2 wd = *reinterpret_cast<const ulonglong2*>(wr + 12);
            float e = (kk == 0) ? ev.x : (kk == 1) ? ev.y : (kk == 2) ? ev.z : ev.w;
            unsigned long long e2; DUP2(e2, e);
            FMA2(acc[0], e2, wa.x, acc[0]); FMA2(acc[1], e2, wa.y, acc[1]);
            FMA2(acc[2], e2, wb.x, acc[2]); FMA2(acc[3], e2, wb.y, acc[3]);
            FMA2(acc[4], e2, wc.x, acc[4]); FMA2(acc[5], e2, wc.y, acc[5]);
            FMA2(acc[6], e2, wd.x, acc[6]); FMA2(acc[7], e2, wd.y, acc[7]);
        }
    }

    // Bias only on the first half (c < 64  <=>  w < 4)
    if (w < 4) {
        ulonglong2 bA = *reinterpret_cast<const ulonglong2*>(&b1[c0]);
        ulonglong2 bB = *reinterpret_cast<const ulonglong2*>(&b1[c0 + 4]);
        ulonglong2 bC = *reinterpret_cast<const ulonglong2*>(&b1[c0 + 8]);
        ulonglong2 bD = *reinterpret_cast<const ulonglong2*>(&b1[c0 + 12]);
        ADD2(acc[0], acc[0], bA.x); ADD2(acc[1], acc[1], bA.y);
        ADD2(acc[2], acc[2], bB.x); ADD2(acc[3], acc[3], bB.y);
        ADD2(acc[4], acc[4], bC.x); ADD2(acc[5], acc[5], bC.y);
        ADD2(acc[6], acc[6], bD.x); ADD2(acc[7], acc[7], bD.y);
    }

    const int node = base + lane;
    if (node < n_nodes) {
        unsigned int h[8];
        #pragma unroll
        for (int j = 0; j < 8; j++) {
            float2 f = unpack2(acc[j]);
            __half2 hv = __floats2half2_rn(f.x, f.y);
            h[j] = *reinterpret_cast<unsigned int*>(&hv);
        }
        uint4 s0 = make_uint4(h[0], h[1], h[2], h[3]);
        uint4 s1 = make_uint4(h[4], h[5], h[6], h[7]);
        *reinterpret_cast<uint4*>(&P[(size_t)node * HID + c0])     = s0;
        *reinterpret_cast<uint4*>(&P[(size_t)node * HID + c0 + 8]) = s1;
    }
}

// ---------------------------------------------------------------------------
// Kernel B: out[e] = relu(P_src[src][0:64] + P_dst[dst][64:128]) . W2 + b2
// Grid-stride over edge quads; W2/b2 live in registers for the warp lifetime.
// 8 lanes/edge, 16B/lane -> perfectly coalesced 128B row reads.
// ---------------------------------------------------------------------------
struct __align__(16) H2x4 { __half2 a, b, c, d; };

__global__ void __launch_bounds__(256) edge_kernel(
    const int* __restrict__ ei,          // [2, E] int32
    const __half* __restrict__ P,
    const float* __restrict__ W2,        // [64]
    const float* __restrict__ b2,        // [1]
    float* __restrict__ out,
    int E)
{
    const int lane = threadIdx.x & 31;
    const int q    = lane & 7;           // position within 8-lane group
    const int grp  = lane >> 3;          // edge within quad
    const int warp0  = (blockIdx.x * blockDim.x + threadIdx.x) >> 5;
    const int nwarps = (gridDim.x * blockDim.x) >> 5;

    const int fo = q * 8;
    const float4 w0 = *reinterpret_cast<const float4*>(&W2[fo]);
    const float4 w1 = *reinterpret_cast<const float4*>(&W2[fo + 4]);
    const float bias = __ldg(b2);
    const __half2 z = __float2half2_rn(0.0f);

    const int nquad = (E + 3) >> 2;
    for (int iq = warp0; iq < nquad; iq += nwarps) {
        const int e  = iq * 4 + grp;
        const int ec = (e < E) ? e : (E - 1);

        const int rs = __ldg(&ei[ec]);
        const int rd = __ldg(&ei[E + ec]);

        const H2x4 av = *reinterpret_cast<const H2x4*>(&P[rs * HID + fo]);
        const H2x4 bv = *reinterpret_cast<const H2x4*>(&P[rd * HID + MLPD + fo]);

        const __half2 h0 = __hmax2(__hadd2(av.a, bv.a), z);
        const __half2 h1 = __hmax2(__hadd2(av.b, bv.b), z);
        const __half2 h2 = __hmax2(__hadd2(av.c, bv.c), z);
        const __half2 h3 = __hmax2(__hadd2(av.d, bv.d), z);

        const float2 f0 = __half22float2(h0);
        const float2 f1 = __half22float2(h1);
        const float2 f2 = __half22float2(h2);
        const float2 f3 = __half22float2(h3);

        float s;
        s = f0.x * w0.x;          s = fmaf(f0.y, w0.y, s);
        s = fmaf(f1.x, w0.z, s);  s = fmaf(f1.y, w0.w, s);
        s = fmaf(f2.x, w1.x, s);  s = fmaf(f2.y, w1.y, s);
        s = fmaf(f3.x, w1.z, s);  s = fmaf(f3.y, w1.w, s);

        s += __shfl_xor_sync(0xffffffffu, s, 4);
        s += __shfl_xor_sync(0xffffffffu, s, 2);
        s += __shfl_xor_sync(0xffffffffu, s, 1);

        if (q == 0 && e < E) out[e] = s + bias;
    }
}

extern "C" void kernel_launch(void* const* d_in, const int* in_sizes, int n_in,
                              void* d_out, int out_size)
{
    // Resolve input slots by element count (robust to metadata ordering).
    int i_emb = 0, i_ei = 1, i_w1 = 2, i_b1 = 3, i_w2 = 4, i_b2 = 5;
    if (n_in == 6) {
        int seen64 = 0;
        for (int i = 0; i < n_in; i++) {
            int s = in_sizes[i];
            if (s == 16384) i_w1 = i;
            else if (s == 1) i_b2 = i;
            else if (s == 64) { if (seen64++ == 0) i_b1 = i; else i_w2 = i; }
            else if (s >= 1000000) {
                if (s > 3000000) i_emb = i; else i_ei = i;
            }
        }
    }
    const float* node_emb = (const float*)d_in[i_emb];
    const int*   edge_idx = (const int*)  d_in[i_ei];
    const float* W1       = (const float*)d_in[i_w1];
    const float* b1       = (const float*)d_in[i_b1];
    const float* W2       = (const float*)d_in[i_w2];
    const float* b2       = (const float*)d_in[i_b2];
    float* out = (float*)d_out;

    const int n_nodes = in_sizes[i_emb] / HID;
    const int E       = in_sizes[i_ei] / 2;

    __half* P = nullptr;
    cudaGetSymbolAddress((void**)&P, g_Ph);

    static bool attr_set = false;
    if (!attr_set) {
        cudaFuncSetAttribute(proj_kernel,
                             cudaFuncAttributeMaxDynamicSharedMemorySize, PROJ_SMEM);
        attr_set = true;
    }

    proj_kernel<<<(n_nodes + TILE_N - 1) / TILE_N, 256, PROJ_SMEM>>>(
        node_emb, W1, b1, P, n_nodes);

    // Persistent-style grid-stride: 1184 blocks x 8 warps
    edge_kernel<<<1184, 256>>>(edge_idx, P, W2, b2, out, E);
}

// round 17
// speedup vs baseline: 1.2444x; 1.2444x over previous
#include <cuda_runtime.h>
#include <cuda_fp16.h>

#define HID 128
#define MLPD 64
#define MAX_NODES 50000
#define TILE_N 32
#define ES_STRIDE 36   // transposed emb tile row stride (floats)

// Scratch: per-node projections in FP16.
// P[n][0:64] = emb[n] @ W1[0:128] + b1 ;  P[n][64:128] = emb[n] @ W1[128:256]
__device__ __half g_Ph[(size_t)MAX_NODES * HID];

#define FMA2(d, a, b, c) \
    asm("fma.rn.f32x2 %0, %1, %2, %3;" : "=l"(d) : "l"(a), "l"(b), "l"(c))
#define ADD2(d, a, b) \
    asm("add.rn.f32x2 %0, %1, %2;" : "=l"(d) : "l"(a), "l"(b))
#define DUP2(d, f) \
    asm("mov.b64 %0, {%1, %1};" : "=l"(d) : "r"(__float_as_uint(f)))

__device__ __forceinline__ float2 unpack2(unsigned long long v) {
    unsigned int lo, hi;
    asm("mov.b64 {%0, %1}, %2;" : "=r"(lo), "=r"(hi) : "l"(v));
    return make_float2(__uint_as_float(lo), __uint_as_float(hi));
}

// ---------------------------------------------------------------------------
// Kernel A: node projection GEMM  [n_nodes,128] x [128,128] -> P (fp16 out)
// R11 structure (measured 47.4us): packed f32x2 FMA, 8 FFMA2/k/thread,
// Es transposed [k][n]. Ws prologue fill vectorized to float4.
// ---------------------------------------------------------------------------
__global__ void __launch_bounds__(128) proj_kernel(
    const float* __restrict__ emb,   // [n_nodes, 128]
    const float* __restrict__ W1,    // [256, 64] row-major
    const float* __restrict__ b1,    // [64]
    __half* __restrict__ P,
    int n_nodes)
{
    __shared__ float Ws[HID * MLPD];            // 32 KB: current half of W1
    __shared__ float Es[HID * ES_STRIDE];       // 18 KB: emb tile, transposed Es[k][n]

    const int tid = threadIdx.x;
    const int base = blockIdx.x * TILE_N;

    // Fill Es transposed: Es[k=tid][n=i]  (coalesced global reads)
    #pragma unroll
    for (int i = 0; i < TILE_N; i++) {
        int node = base + i;
        float v = (node < n_nodes) ? emb[(size_t)node * HID + tid] : 0.0f;
        Es[tid * ES_STRIDE + i] = v;
    }

    const int jg = tid & 15;          // 16 j-groups of 4 outputs
    const int ng = tid >> 4;          // 8 n-groups of 4 nodes
    const int jbase = jg * 4;
    const int nbase = ng * 4;

    for (int half = 0; half < 2; half++) {
        __syncthreads();
        // Vectorized Ws fill: 2048 float4 per half, 128 threads -> 16 iters
        {
            const float4* src = reinterpret_cast<const float4*>(W1 + half * (HID * MLPD));
            float4* dst = reinterpret_cast<float4*>(Ws);
            #pragma unroll
            for (int i = 0; i < (HID * MLPD) / (128 * 4); i++)
                dst[i * 128 + tid] = src[i * 128 + tid];
        }
        __syncthreads();

        unsigned long long acc[4][2];
        #pragma unroll
        for (int t = 0; t < 4; t++) { acc[t][0] = 0ull; acc[t][1] = 0ull; }

        #pragma unroll 4
        for (int k = 0; k < HID; k++) {
            // w pair-packed for free: float4 bits == {f32x2, f32x2}
            ulonglong2 wp = *reinterpret_cast<const ulonglong2*>(&Ws[k * MLPD + jbase]);
            float4 ev = *reinterpret_cast<const float4*>(&Es[k * ES_STRIDE + nbase]);
            unsigned long long e0, e1, e2, e3;
            DUP2(e0, ev.x); DUP2(e1, ev.y); DUP2(e2, ev.z); DUP2(e3, ev.w);
            FMA2(acc[0][0], e0, wp.x, acc[0][0]); FMA2(acc[0][1], e0, wp.y, acc[0][1]);
            FMA2(acc[1][0], e1, wp.x, acc[1][0]); FMA2(acc[1][1], e1, wp.y, acc[1][1]);
            FMA2(acc[2][0], e2, wp.x, acc[2][0]); FMA2(acc[2][1], e2, wp.y, acc[2][1]);
            FMA2(acc[3][0], e3, wp.x, acc[3][0]); FMA2(acc[3][1], e3, wp.y, acc[3][1]);
        }

        if (half == 0) {
            ulonglong2 bp = *reinterpret_cast<const ulonglong2*>(&b1[jbase]);
            #pragma unroll
            for (int t = 0; t < 4; t++) {
                ADD2(acc[t][0], acc[t][0], bp.x);
                ADD2(acc[t][1], acc[t][1], bp.y);
            }
        }

        #pragma unroll
        for (int t = 0; t < 4; t++) {
            int node = base + nbase + t;
            if (node < n_nodes) {
                float2 lo = unpack2(acc[t][0]);
                float2 hi = unpack2(acc[t][1]);
                __half2 h0 = __floats2half2_rn(lo.x, lo.y);
                __half2 h1 = __floats2half2_rn(hi.x, hi.y);
                uint2 st;
                st.x = *reinterpret_cast<unsigned int*>(&h0);
                st.y = *reinterpret_cast<unsigned int*>(&h1);
                *reinterpret_cast<uint2*>(&P[(size_t)node * HID + half * MLPD + jbase]) = st;
            }
        }
    }
}

// ---------------------------------------------------------------------------
// Kernel B: out[e] = relu(P_src[src][0:64] + P_dst[dst][64:128]) . W2 + b2
// Grid-stride over edge quads; W2/b2 register-resident for the warp lifetime.
// 8 lanes/edge, 16B/lane -> coalesced 128B row reads. (measured 32.4us)
// ---------------------------------------------------------------------------
struct __align__(16) H2x4 { __half2 a, b, c, d; };

__global__ void __launch_bounds__(256) edge_kernel(
    const int* __restrict__ ei,          // [2, E] int32
    const __half* __restrict__ P,
    const float* __restrict__ W2,        // [64]
    const float* __restrict__ b2,        // [1]
    float* __restrict__ out,
    int E)
{
    const int lane = threadIdx.x & 31;
    const int q    = lane & 7;           // position within 8-lane group
    const int grp  = lane >> 3;          // edge within quad
    const int warp0  = (blockIdx.x * blockDim.x + threadIdx.x) >> 5;
    const int nwarps = (gridDim.x * blockDim.x) >> 5;

    const int fo = q * 8;
    const float4 w0 = *reinterpret_cast<const float4*>(&W2[fo]);
    const float4 w1 = *reinterpret_cast<const float4*>(&W2[fo + 4]);
    const float bias = __ldg(b2);
    const __half2 z = __float2half2_rn(0.0f);

    const int nquad = (E + 3) >> 2;
    for (int iq = warp0; iq < nquad; iq += nwarps) {
        const int e  = iq * 4 + grp;
        const int ec = (e < E) ? e : (E - 1);

        const int rs = __ldg(&ei[ec]);
        const int rd = __ldg(&ei[E + ec]);

        const H2x4 av = *reinterpret_cast<const H2x4*>(&P[rs * HID + fo]);
        const H2x4 bv = *reinterpret_cast<const H2x4*>(&P[rd * HID + MLPD + fo]);

        const __half2 h0 = __hmax2(__hadd2(av.a, bv.a), z);
        const __half2 h1 = __hmax2(__hadd2(av.b, bv.b), z);
        const __half2 h2 = __hmax2(__hadd2(av.c, bv.c), z);
        const __half2 h3 = __hmax2(__hadd2(av.d, bv.d), z);

        const float2 f0 = __half22float2(h0);
        const float2 f1 = __half22float2(h1);
        const float2 f2 = __half22float2(h2);
        const float2 f3 = __half22float2(h3);

        float s;
        s = f0.x * w0.x;          s = fmaf(f0.y, w0.y, s);
        s = fmaf(f1.x, w0.z, s);  s = fmaf(f1.y, w0.w, s);
        s = fmaf(f2.x, w1.x, s);  s = fmaf(f2.y, w1.y, s);
        s = fmaf(f3.x, w1.z, s);  s = fmaf(f3.y, w1.w, s);

        s += __shfl_xor_sync(0xffffffffu, s, 4);
        s += __shfl_xor_sync(0xffffffffu, s, 2);
        s += __shfl_xor_sync(0xffffffffu, s, 1);

        if (q == 0 && e < E) out[e] = s + bias;
    }
}

extern "C" void kernel_launch(void* const* d_in, const int* in_sizes, int n_in,
                              void* d_out, int out_size)
{
    // Resolve input slots by element count (robust to metadata ordering).
    int i_emb = 0, i_ei = 1, i_w1 = 2, i_b1 = 3, i_w2 = 4, i_b2 = 5;
    if (n_in == 6) {
        int seen64 = 0;
        for (int i = 0; i < n_in; i++) {
            int s = in_sizes[i];
            if (s == 16384) i_w1 = i;
            else if (s == 1) i_b2 = i;
            else if (s == 64) { if (seen64++ == 0) i_b1 = i; else i_w2 = i; }
            else if (s >= 1000000) {
                if (s > 3000000) i_emb = i; else i_ei = i;
            }
        }
    }
    const float* node_emb = (const float*)d_in[i_emb];
    const int*   edge_idx = (const int*)  d_in[i_ei];
    const float* W1       = (const float*)d_in[i_w1];
    const float* b1       = (const float*)d_in[i_b1];
    const float* W2       = (const float*)d_in[i_w2];
    const float* b2       = (const float*)d_in[i_b2];
    float* out = (float*)d_out;

    const int n_nodes = in_sizes[i_emb] / HID;
    const int E       = in_sizes[i_ei] / 2;

    __half* P = nullptr;
    cudaGetSymbolAddress((void**)&P, g_Ph);

    proj_kernel<<<(n_nodes + TILE_N - 1) / TILE_N, 128>>>(node_emb, W1, b1, P, n_nodes);

    // Persistent-style grid-stride: 1184 blocks x 8 warps
    edge_kernel<<<1184, 256>>>(edge_idx, P, W2, b2, out, E);
}